// round 1
// baseline (speedup 1.0000x reference)
#include <cuda_runtime.h>

// Fused 3-layer GraphConv, B=524288 elements, per-thread element with
// shared-memory staged coalesced I/O.
//
// Graph constants (from reference _build_graphs):
//   A_ENC:  agg[j]  = sum_{i=4j-3..4j+2} x[i mod 40]
//   A_PRED: agg2[j] = z1[j] + w*(z1[j-1] + z1[j+1]),  w = exp(-1/9)
//   A_DEC:  out[4k]=s[k], out[4k+1]=out[4k+2]=s[k]+s[k+1], out[4k+3]=s[k+1]
//           where s[j] = dot(z2[j], dec_rel_w)

#define WPRED 0.8948393168143698f

__global__ void __launch_bounds__(128, 3)
fused_gnn_kernel(const float* __restrict__ x,
                 const float* __restrict__ z,
                 const float* __restrict__ y,
                 const float* __restrict__ enc_rel_w,
                 const float* __restrict__ enc_rel_b,
                 const float* __restrict__ enc_root_w,
                 const float* __restrict__ pred_rel_w,
                 const float* __restrict__ pred_rel_b,
                 const float* __restrict__ pred_root_w,
                 const float* __restrict__ dec_rel_w,
                 const float* __restrict__ dec_rel_b,
                 const float* __restrict__ dec_root_w,
                 float* __restrict__ out,
                 long long B)
{
    __shared__ __align__(16) float wsm[232];
    __shared__ float4 sbuf4[4][672];   // 2688 floats per warp (z tile: 32 rows x 84)

    const int tid = threadIdx.x;
    // ---- stage weights into shared (once per block) ----
    if (tid < 64) {
        wsm[tid]       = enc_root_w[tid];   // [f][g] row-major 8x8
        wsm[64 + tid]  = pred_rel_w[tid];
        wsm[128 + tid] = pred_root_w[tid];
    }
    if (tid < 8) {
        wsm[192 + tid] = enc_rel_w[tid];    // [8,1]
        wsm[200 + tid] = enc_rel_b[tid];
        wsm[208 + tid] = pred_rel_b[tid];
        wsm[216 + tid] = dec_rel_w[tid];    // [1,8]
    }
    if (tid == 0) { wsm[224] = dec_rel_b[0]; wsm[225] = dec_root_w[0]; }
    __syncthreads();

    const int warp = tid >> 5;
    const int lane = tid & 31;
    const long long e0 = ((long long)blockIdx.x * 4 + warp) * 32;  // first element of warp tile
    if (e0 >= B) return;
    const int nval = (B - e0 >= 32) ? 32 : (int)(B - e0);
    float* buf = (float*)sbuf4[warp];

    // =========== stage x (coalesced) : rows padded to 44 floats ===========
    {
        const float4* xg = (const float4*)(x + e0 * 40);
        const int lim = nval * 10;
        #pragma unroll
        for (int k = 0; k < 10; k++) {
            int f4 = k * 32 + lane;
            if (f4 < lim) {
                float4 v = xg[f4];
                int e = f4 / 10, c = f4 % 10;
                *(float4*)&buf[e * 44 + c * 4] = v;
            }
        }
    }
    __syncwarp();

    float agg[10];
    if (lane < nval) {
        float xr[40];
        const float4* myx = (const float4*)&buf[lane * 44];
        #pragma unroll
        for (int k = 0; k < 10; k++) {
            float4 v = myx[k];
            xr[4*k] = v.x; xr[4*k+1] = v.y; xr[4*k+2] = v.z; xr[4*k+3] = v.w;
        }
        float p[20];
        #pragma unroll
        for (int i = 0; i < 20; i++) p[i] = xr[2*i] + xr[2*i+1];
        #pragma unroll
        for (int j = 0; j < 10; j++) {
            const int a  = (4*j - 3 + 40) % 40;  // x[4j-3]
            const int b  = (4*j + 2) % 40;       // x[4j+2]
            const int pm = (2*j - 1 + 20) % 20;  // x[4j-2]+x[4j-1]
            agg[j] = xr[a] + p[pm] + p[2*j] + xr[b];
        }
    }
    __syncwarp();   // x region of buf free

    // =========== stage z (coalesced) : rows padded to 84 floats ===========
    {
        const float4* zg = (const float4*)(z + e0 * 80);
        const int lim = nval * 20;
        #pragma unroll
        for (int k = 0; k < 20; k++) {
            int f4 = k * 32 + lane;
            if (f4 < lim) {
                float4 v = zg[f4];
                int e = f4 / 20, c = f4 % 20;
                *(float4*)&buf[e * 84 + c * 4] = v;
            }
        }
    }
    __syncwarp();

    float s[10];
    if (lane < nval) {
        // ---- encoder: z1[j][f] = relu(agg[j]*erw[f] + erb[f] + z[j].eroot_row[f]) ----
        float z1[80];
        const float4* er4 = (const float4*)&wsm[0];
        #pragma unroll
        for (int j = 0; j < 10; j++) {
            float4 za = *(const float4*)&buf[lane * 84 + j * 8];
            float4 zb = *(const float4*)&buf[lane * 84 + j * 8 + 4];
            #pragma unroll
            for (int f = 0; f < 8; f++) {
                float4 wa = er4[f * 2], wb = er4[f * 2 + 1];
                float t = fmaf(agg[j], wsm[192 + f], wsm[200 + f]);
                t = fmaf(za.x, wa.x, t); t = fmaf(za.y, wa.y, t);
                t = fmaf(za.z, wa.z, t); t = fmaf(za.w, wa.w, t);
                t = fmaf(zb.x, wb.x, t); t = fmaf(zb.y, wb.y, t);
                t = fmaf(zb.z, wb.z, t); t = fmaf(zb.w, wb.w, t);
                z1[j * 8 + f] = fmaxf(t, 0.0f);
            }
        }

        // ---- predictor + fold dec_rel into scalar s[j] ----
        const float4* pr4 = (const float4*)&wsm[64];
        const float4* po4 = (const float4*)&wsm[128];
        #pragma unroll
        for (int j = 0; j < 10; j++) {
            const int jm = (j + 9) % 10, jp = (j + 1) % 10;
            float a2[8];
            #pragma unroll
            for (int g = 0; g < 8; g++)
                a2[g] = fmaf(WPRED, z1[jm * 8 + g] + z1[jp * 8 + g], z1[j * 8 + g]);
            float sj = 0.0f;
            #pragma unroll
            for (int f = 0; f < 8; f++) {
                float4 ra = pr4[f * 2], rb = pr4[f * 2 + 1];
                float4 oa = po4[f * 2], ob = po4[f * 2 + 1];
                float t = wsm[208 + f];
                t = fmaf(a2[0], ra.x, t); t = fmaf(a2[1], ra.y, t);
                t = fmaf(a2[2], ra.z, t); t = fmaf(a2[3], ra.w, t);
                t = fmaf(a2[4], rb.x, t); t = fmaf(a2[5], rb.y, t);
                t = fmaf(a2[6], rb.z, t); t = fmaf(a2[7], rb.w, t);
                t = fmaf(z1[j*8+0], oa.x, t); t = fmaf(z1[j*8+1], oa.y, t);
                t = fmaf(z1[j*8+2], oa.z, t); t = fmaf(z1[j*8+3], oa.w, t);
                t = fmaf(z1[j*8+4], ob.x, t); t = fmaf(z1[j*8+5], ob.y, t);
                t = fmaf(z1[j*8+6], ob.z, t); t = fmaf(z1[j*8+7], ob.w, t);
                t = fmaxf(t, 0.0f);
                sj = fmaf(t, wsm[216 + f], sj);
            }
            s[j] = sj;
        }
    }
    __syncwarp();   // z region of buf free

    // =========== stage y, compute out in place, store coalesced ===========
    {
        const float4* yg = (const float4*)(y + e0 * 40);
        const int lim = nval * 10;
        #pragma unroll
        for (int k = 0; k < 10; k++) {
            int f4 = k * 32 + lane;
            if (f4 < lim) {
                float4 v = yg[f4];
                int e = f4 / 10, c = f4 % 10;
                *(float4*)&buf[e * 44 + c * 4] = v;
            }
        }
    }
    __syncwarp();

    if (lane < nval) {
        const float drb = wsm[224], drt = wsm[225];
        float4* myrow = (float4*)&buf[lane * 44];
        #pragma unroll
        for (int k = 0; k < 10; k++) {
            const int kp = (k + 1) % 10;
            const float c0 = s[k], c3 = s[kp];
            const float c12 = s[k] + s[kp];
            float4 v = myrow[k];
            v.x = fmaf(v.x, drt, drb) + c0;
            v.y = fmaf(v.y, drt, drb) + c12;
            v.z = fmaf(v.z, drt, drb) + c12;
            v.w = fmaf(v.w, drt, drb) + c3;
            myrow[k] = v;
        }
    }
    __syncwarp();

    {
        float4* og = (float4*)(out + e0 * 40);
        const int lim = nval * 10;
        #pragma unroll
        for (int k = 0; k < 10; k++) {
            int f4 = k * 32 + lane;
            if (f4 < lim) {
                int e = f4 / 10, c = f4 % 10;
                og[f4] = *(const float4*)&buf[e * 44 + c * 4];
            }
        }
    }
}

extern "C" void kernel_launch(void* const* d_in, const int* in_sizes, int n_in,
                              void* d_out, int out_size)
{
    const float* x          = (const float*)d_in[0];
    const float* z          = (const float*)d_in[1];
    const float* y          = (const float*)d_in[2];
    const float* enc_rel_w  = (const float*)d_in[3];
    const float* enc_rel_b  = (const float*)d_in[4];
    const float* enc_root_w = (const float*)d_in[5];
    const float* pred_rel_w = (const float*)d_in[6];
    const float* pred_rel_b = (const float*)d_in[7];
    const float* pred_root_w= (const float*)d_in[8];
    const float* dec_rel_w  = (const float*)d_in[9];
    const float* dec_rel_b  = (const float*)d_in[10];
    const float* dec_root_w = (const float*)d_in[11];

    const long long B = (long long)in_sizes[0] / 40;
    const int threads = 128;                       // 4 warps x 32 elements
    const long long elems_per_block = 128;
    const int blocks = (int)((B + elems_per_block - 1) / elems_per_block);

    fused_gnn_kernel<<<blocks, threads>>>(
        x, z, y, enc_rel_w, enc_rel_b, enc_root_w,
        pred_rel_w, pred_rel_b, pred_root_w,
        dec_rel_w, dec_rel_b, dec_root_w,
        (float*)d_out, B);
}